// round 6
// baseline (speedup 1.0000x reference)
#include <cuda_runtime.h>
#include <cuda_bf16.h>
#include <cstdint>

// GriddingDistance round 6: round-5 scatter (z-window vector REDs) + forked
// stream capture to overlap the serial chain:
//   default: memset_pred -> scatterP_A(55%) -> scatterP_B(45%) -> join
//   side   : memset_gt (|| scatterP_A) -> scatterG (|| scatterP_B)

#define GRID_R 128

__device__ __forceinline__ void red_add_f32(float* p, float v) {
    atomicAdd(p, v);  // return unused -> REDG
}

__device__ __forceinline__ void red_add_v2_f32(float* p, float a, float b) {
    asm volatile("red.global.add.v2.f32 [%0], {%1, %2};"
                 :: "l"(p), "f"(a), "f"(b) : "memory");
}

__device__ __forceinline__ void red_add_v4_f32(float* p, float a, float b,
                                               float c, float d) {
    asm volatile("red.global.add.v4.f32 [%0], {%1, %2, %3, %4};"
                 :: "l"(p), "f"(a), "f"(b), "f"(c), "f"(d) : "memory");
}

__global__ __launch_bounds__(256)
void scatter_kernel(const float* __restrict__ pts,
                    float* __restrict__ g,
                    int n_per_sample,
                    int start,
                    int count)
{
    int t = blockIdx.x * blockDim.x + threadIdx.x;
    if (t >= count) return;
    t += start;

    float px = fmaf(pts[3 * t + 0], 128.0f, 64.0f);
    float py = fmaf(pts[3 * t + 1], 128.0f, 64.0f);
    float pz = fmaf(pts[3 * t + 2], 128.0f, 64.0f);

    float fx = floorf(px), fy = floorf(py), fz = floorf(pz);
    float dx = px - fx,   dy = py - fy,   dz = pz - fz;

    int ix = (int)fx, iy = (int)fy, iz = (int)fz;

    float wx0 = 1.0f - dx, wy0 = 1.0f - dy, wz0 = 1.0f - dz;
    float w00 = wx0 * wy0;
    float w01 = wx0 * dy;
    float w10 = dx  * wy0;
    float w11 = dx  * dy;

    int sample = t / n_per_sample;
    float* __restrict__ gb = g + (long long)sample * (GRID_R * GRID_R * GRID_R);

    bool interior = (ix >= 0) & (ix + 1 < GRID_R) &
                    (iy >= 0) & (iy + 1 < GRID_R) &
                    (iz >= 0) & (iz + 1 < GRID_R);

    if (interior) {
        int r00 = (ix * GRID_R + iy) * GRID_R + iz;
        int r01 = r00 + GRID_R;
        int r10 = r00 + GRID_R * GRID_R;
        int r11 = r10 + GRID_R;

        int m4 = iz & 3;
        if ((m4 & 1) == 0) {
            red_add_v2_f32(gb + r00, w00 * wz0, w00 * dz);
            red_add_v2_f32(gb + r01, w01 * wz0, w01 * dz);
            red_add_v2_f32(gb + r10, w10 * wz0, w10 * dz);
            red_add_v2_f32(gb + r11, w11 * wz0, w11 * dz);
        } else if (m4 == 1) {
            red_add_v4_f32(gb + r00 - 1, 0.f, w00 * wz0, w00 * dz, 0.f);
            red_add_v4_f32(gb + r01 - 1, 0.f, w01 * wz0, w01 * dz, 0.f);
            red_add_v4_f32(gb + r10 - 1, 0.f, w10 * wz0, w10 * dz, 0.f);
            red_add_v4_f32(gb + r11 - 1, 0.f, w11 * wz0, w11 * dz, 0.f);
        } else {
            red_add_f32(gb + r00,     w00 * wz0);
            red_add_f32(gb + r00 + 1, w00 * dz);
            red_add_f32(gb + r01,     w01 * wz0);
            red_add_f32(gb + r01 + 1, w01 * dz);
            red_add_f32(gb + r10,     w10 * wz0);
            red_add_f32(gb + r10 + 1, w10 * dz);
            red_add_f32(gb + r11,     w11 * wz0);
            red_add_f32(gb + r11 + 1, w11 * dz);
        }
    } else {
        int ix0 = min(max(ix,     0), GRID_R - 1);
        int ix1 = min(max(ix + 1, 0), GRID_R - 1);
        int iy0 = min(max(iy,     0), GRID_R - 1);
        int iy1 = min(max(iy + 1, 0), GRID_R - 1);
        int iz0 = min(max(iz,     0), GRID_R - 1);
        int iz1 = min(max(iz + 1, 0), GRID_R - 1);
        int rx0 = ix0 * GRID_R * GRID_R, rx1 = ix1 * GRID_R * GRID_R;
        int ry0 = iy0 * GRID_R,          ry1 = iy1 * GRID_R;
        red_add_f32(gb + (rx0 + ry0 + iz0), w00 * wz0);
        red_add_f32(gb + (rx0 + ry0 + iz1), w00 * dz);
        red_add_f32(gb + (rx0 + ry1 + iz0), w01 * wz0);
        red_add_f32(gb + (rx0 + ry1 + iz1), w01 * dz);
        red_add_f32(gb + (rx1 + ry0 + iz0), w10 * wz0);
        red_add_f32(gb + (rx1 + ry0 + iz1), w10 * dz);
        red_add_f32(gb + (rx1 + ry1 + iz0), w11 * wz0);
        red_add_f32(gb + (rx1 + ry1 + iz1), w11 * dz);
    }
}

extern "C" void kernel_launch(void* const* d_in, const int* in_sizes, int n_in,
                              void* d_out, int out_size)
{
    const float* pred = (const float*)d_in[0];
    const float* gt   = (const float*)d_in[1];
    float* out = (float*)d_out;

    const int G = GRID_R * GRID_R * GRID_R;            // 2097152
    int b = out_size / (2 * G);                        // 8
    int total_points = in_sizes[0] / 3;                // 524288
    int n = total_points / b;                          // 65536
    long long grid_per_cloud = (long long)b * G;       // 16777216 floats

    // one-time resource init (no per-call work difference)
    static cudaStream_t sB = nullptr;
    static cudaEvent_t e0 = nullptr, e1 = nullptr, e3 = nullptr;
    if (!sB) {
        cudaStreamCreateWithFlags(&sB, cudaStreamNonBlocking);
        cudaEventCreateWithFlags(&e0, cudaEventDisableTiming);
        cudaEventCreateWithFlags(&e1, cudaEventDisableTiming);
        cudaEventCreateWithFlags(&e3, cudaEventDisableTiming);
    }

    int nA = (total_points * 55) / 100;                // first 55% of pred
    nA = (nA + 255) & ~255;                            // block-align
    int nB = total_points - nA;

    // Phase 1 (default): zero pred half
    cudaMemsetAsync(out, 0, (size_t)grid_per_cloud * sizeof(float));
    cudaEventRecord(e0, 0);

    // Side stream: zero gt half (overlaps pred scatter A)
    cudaStreamWaitEvent(sB, e0, 0);
    cudaMemsetAsync(out + grid_per_cloud, 0,
                    (size_t)grid_per_cloud * sizeof(float), sB);

    // Default: pred scatter part A
    scatter_kernel<<<(nA + 255) / 256, 256>>>(pred, out, n, 0, nA);
    cudaEventRecord(e1, 0);

    // Default: pred scatter part B (overlaps gt scatter)
    scatter_kernel<<<(nB + 255) / 256, 256>>>(pred, out, n, nA, nB);

    // Side stream: gt scatter after gt-zero (in-order on sB) and scatterP_A
    cudaStreamWaitEvent(sB, e1, 0);
    scatter_kernel<<<(total_points + 255) / 256, 256, 0, sB>>>(
        gt, out + grid_per_cloud, n, 0, total_points);
    cudaEventRecord(e3, sB);

    // Join back into the captured default stream
    cudaStreamWaitEvent(0, e3, 0);
}

// round 7
// speedup vs baseline: 1.3347x; 1.3347x over previous
#include <cuda_runtime.h>
#include <cuda_bf16.h>
#include <cstdint>

// GriddingDistance round 7: single-stream chunk pipeline. Job is split into
// 2*(b/2) chunks of (cloud, sample-pair) = 16MB grid + 128K points each.
// Launch k scatters chunk k while zeroing chunk k+1 (blockIdx.y role split),
// so only chunk 0's zero-fill is exposed. One working set hot at a time
// (L2-residency invariant from round 3 preserved; no cross-stream overlap).

#define GRID_R 128
#define GSZ    (GRID_R * GRID_R * GRID_R)

__device__ __forceinline__ void red_add_f32(float* p, float v) {
    atomicAdd(p, v);  // return unused -> REDG
}

__device__ __forceinline__ void red_add_v2_f32(float* p, float a, float b) {
    asm volatile("red.global.add.v2.f32 [%0], {%1, %2};"
                 :: "l"(p), "f"(a), "f"(b) : "memory");
}

__device__ __forceinline__ void red_add_v4_f32(float* p, float a, float b,
                                               float c, float d) {
    asm volatile("red.global.add.v4.f32 [%0], {%1, %2, %3, %4};"
                 :: "l"(p), "f"(a), "f"(b), "f"(c), "f"(d) : "memory");
}

__device__ __forceinline__ void scatter_range(const float* __restrict__ pts,
                                              float* __restrict__ g,   // cloud grid base
                                              int n_per_sample,
                                              int start, int count)
{
    int t = blockIdx.x * blockDim.x + threadIdx.x;
    if (t >= count) return;
    t += start;

    float px = fmaf(pts[3 * t + 0], 128.0f, 64.0f);
    float py = fmaf(pts[3 * t + 1], 128.0f, 64.0f);
    float pz = fmaf(pts[3 * t + 2], 128.0f, 64.0f);

    float fx = floorf(px), fy = floorf(py), fz = floorf(pz);
    float dx = px - fx,   dy = py - fy,   dz = pz - fz;

    int ix = (int)fx, iy = (int)fy, iz = (int)fz;

    float wx0 = 1.0f - dx, wy0 = 1.0f - dy, wz0 = 1.0f - dz;
    float w00 = wx0 * wy0;
    float w01 = wx0 * dy;
    float w10 = dx  * wy0;
    float w11 = dx  * dy;

    int sample = t / n_per_sample;
    float* __restrict__ gb = g + (long long)sample * GSZ;

    bool interior = (ix >= 0) & (ix + 1 < GRID_R) &
                    (iy >= 0) & (iy + 1 < GRID_R) &
                    (iz >= 0) & (iz + 1 < GRID_R);

    if (interior) {
        int r00 = (ix * GRID_R + iy) * GRID_R + iz;
        int r01 = r00 + GRID_R;
        int r10 = r00 + GRID_R * GRID_R;
        int r11 = r10 + GRID_R;

        int m4 = iz & 3;
        if ((m4 & 1) == 0) {
            red_add_v2_f32(gb + r00, w00 * wz0, w00 * dz);
            red_add_v2_f32(gb + r01, w01 * wz0, w01 * dz);
            red_add_v2_f32(gb + r10, w10 * wz0, w10 * dz);
            red_add_v2_f32(gb + r11, w11 * wz0, w11 * dz);
        } else if (m4 == 1) {
            red_add_v4_f32(gb + r00 - 1, 0.f, w00 * wz0, w00 * dz, 0.f);
            red_add_v4_f32(gb + r01 - 1, 0.f, w01 * wz0, w01 * dz, 0.f);
            red_add_v4_f32(gb + r10 - 1, 0.f, w10 * wz0, w10 * dz, 0.f);
            red_add_v4_f32(gb + r11 - 1, 0.f, w11 * wz0, w11 * dz, 0.f);
        } else {
            red_add_f32(gb + r00,     w00 * wz0);
            red_add_f32(gb + r00 + 1, w00 * dz);
            red_add_f32(gb + r01,     w01 * wz0);
            red_add_f32(gb + r01 + 1, w01 * dz);
            red_add_f32(gb + r10,     w10 * wz0);
            red_add_f32(gb + r10 + 1, w10 * dz);
            red_add_f32(gb + r11,     w11 * wz0);
            red_add_f32(gb + r11 + 1, w11 * dz);
        }
    } else {
        int ix0 = min(max(ix,     0), GRID_R - 1);
        int ix1 = min(max(ix + 1, 0), GRID_R - 1);
        int iy0 = min(max(iy,     0), GRID_R - 1);
        int iy1 = min(max(iy + 1, 0), GRID_R - 1);
        int iz0 = min(max(iz,     0), GRID_R - 1);
        int iz1 = min(max(iz + 1, 0), GRID_R - 1);
        int rx0 = ix0 * GRID_R * GRID_R, rx1 = ix1 * GRID_R * GRID_R;
        int ry0 = iy0 * GRID_R,          ry1 = iy1 * GRID_R;
        red_add_f32(gb + (rx0 + ry0 + iz0), w00 * wz0);
        red_add_f32(gb + (rx0 + ry0 + iz1), w00 * dz);
        red_add_f32(gb + (rx0 + ry1 + iz0), w01 * wz0);
        red_add_f32(gb + (rx0 + ry1 + iz1), w01 * dz);
        red_add_f32(gb + (rx1 + ry0 + iz0), w10 * wz0);
        red_add_f32(gb + (rx1 + ry0 + iz1), w10 * dz);
        red_add_f32(gb + (rx1 + ry1 + iz0), w11 * wz0);
        red_add_f32(gb + (rx1 + ry1 + iz1), w11 * dz);
    }
}

// Launch c: y==0 blocks scatter chunk c; y==1 blocks zero chunk c+1.
// chunk -> cloud = chunk / pp, pair = chunk % pp (pp = b/2 sample-pairs).
__global__ __launch_bounds__(256)
void scatter_zero_kernel(const float* __restrict__ pred,
                         const float* __restrict__ gt,
                         float* __restrict__ out,
                         int n_per_sample,
                         int chunk, int pp,
                         long long grid_per_cloud)
{
    if (blockIdx.y == 0) {
        int cloud = chunk / pp;
        int pair  = chunk - cloud * pp;
        const float* pts = cloud ? gt : pred;
        float* g = out + (long long)cloud * grid_per_cloud;
        scatter_range(pts, g, n_per_sample,
                      pair * 2 * n_per_sample, 2 * n_per_sample);
    } else {
        int c2    = chunk + 1;
        int cloud = c2 / pp;
        int pair  = c2 - cloud * pp;
        float* zbase = out + (long long)cloud * grid_per_cloud
                           + (long long)pair * 2 * GSZ;
        float4* z = (float4*)zbase;
        long long n4 = (2LL * GSZ) >> 2;
        long long nthreads = (long long)gridDim.x * blockDim.x;
        float4 zero = make_float4(0.f, 0.f, 0.f, 0.f);
        for (long long i = (long long)blockIdx.x * blockDim.x + threadIdx.x;
             i < n4; i += nthreads)
            z[i] = zero;
    }
}

extern "C" void kernel_launch(void* const* d_in, const int* in_sizes, int n_in,
                              void* d_out, int out_size)
{
    const float* pred = (const float*)d_in[0];
    const float* gt   = (const float*)d_in[1];
    float* out = (float*)d_out;

    int b = out_size / (2 * GSZ);                      // 8
    int total_points = in_sizes[0] / 3;                // 524288
    int n = total_points / b;                          // 65536
    long long grid_per_cloud = (long long)b * GSZ;     // 16777216 floats

    int pp = b / 2;                                    // sample-pairs per cloud (4)
    int nchunks = 2 * pp;                              // 8

    if (pp == 0) {
        // degenerate fallback (b == 1): round-5 style two-phase schedule
        cudaMemsetAsync(out, 0, (size_t)out_size * sizeof(float));
        // single chunked scatter per cloud via the same kernel, pp=1 semantics
        // (not exercised by this dataset)
        pp = 1; nchunks = 2;
        scatter_zero_kernel<<<dim3((n + 255) / 256, 1), 256>>>(
            pred, gt, out, n, 0, pp, grid_per_cloud);
        scatter_zero_kernel<<<dim3((n + 255) / 256, 1), 256>>>(
            pred, gt, out, n, 1, pp, grid_per_cloud);
        return;
    }

    int pts_per_chunk = 2 * n;                         // 131072
    int nblk = (pts_per_chunk + 255) / 256;            // 512

    // expose only chunk 0's zero-fill (16 MB)
    cudaMemsetAsync(out, 0, (size_t)(2LL * GSZ) * sizeof(float));

    for (int c = 0; c < nchunks; c++) {
        dim3 grid(nblk, (c < nchunks - 1) ? 2 : 1);
        scatter_zero_kernel<<<grid, 256>>>(pred, gt, out, n, c, pp,
                                           grid_per_cloud);
    }
}

// round 8
// speedup vs baseline: 1.5399x; 1.1538x over previous
#include <cuda_runtime.h>
#include <cuda_bf16.h>
#include <cstdint>

// GriddingDistance round 8: round-5 schedule with ONE extra split to shrink
// the exposed zero-fill:
//   L0 memset pred samples[0,2)   (16MB exposed)
//   L1 scatter pred pts of samples[0,2)  || zero pred samples[2,b)
//   L2 scatter pred pts of samples[2,b)  || zero gt half
//   L3 scatter gt (all)
// Scatter math identical to the round-5 winner (z-window v2/v4 REDs).

#define GRID_R 128
#define GSZ    (GRID_R * GRID_R * GRID_R)

__device__ __forceinline__ void red_add_f32(float* p, float v) {
    atomicAdd(p, v);  // return unused -> REDG
}

__device__ __forceinline__ void red_add_v2_f32(float* p, float a, float b) {
    asm volatile("red.global.add.v2.f32 [%0], {%1, %2};"
                 :: "l"(p), "f"(a), "f"(b) : "memory");
}

__device__ __forceinline__ void red_add_v4_f32(float* p, float a, float b,
                                               float c, float d) {
    asm volatile("red.global.add.v4.f32 [%0], {%1, %2, %3, %4};"
                 :: "l"(p), "f"(a), "f"(b), "f"(c), "f"(d) : "memory");
}

__device__ __forceinline__ void scatter_range(const float* __restrict__ pts,
                                              float* __restrict__ g,
                                              int n_per_sample,
                                              int start, int count)
{
    int t = blockIdx.x * blockDim.x + threadIdx.x;
    if (t >= count) return;
    t += start;

    float px = fmaf(pts[3 * t + 0], 128.0f, 64.0f);
    float py = fmaf(pts[3 * t + 1], 128.0f, 64.0f);
    float pz = fmaf(pts[3 * t + 2], 128.0f, 64.0f);

    float fx = floorf(px), fy = floorf(py), fz = floorf(pz);
    float dx = px - fx,   dy = py - fy,   dz = pz - fz;

    int ix = (int)fx, iy = (int)fy, iz = (int)fz;

    float wx0 = 1.0f - dx, wy0 = 1.0f - dy, wz0 = 1.0f - dz;
    float w00 = wx0 * wy0;
    float w01 = wx0 * dy;
    float w10 = dx  * wy0;
    float w11 = dx  * dy;

    int sample = t / n_per_sample;
    float* __restrict__ gb = g + (long long)sample * GSZ;

    bool interior = (ix >= 0) & (ix + 1 < GRID_R) &
                    (iy >= 0) & (iy + 1 < GRID_R) &
                    (iz >= 0) & (iz + 1 < GRID_R);

    if (interior) {
        int r00 = (ix * GRID_R + iy) * GRID_R + iz;
        int r01 = r00 + GRID_R;
        int r10 = r00 + GRID_R * GRID_R;
        int r11 = r10 + GRID_R;

        int m4 = iz & 3;
        if ((m4 & 1) == 0) {
            red_add_v2_f32(gb + r00, w00 * wz0, w00 * dz);
            red_add_v2_f32(gb + r01, w01 * wz0, w01 * dz);
            red_add_v2_f32(gb + r10, w10 * wz0, w10 * dz);
            red_add_v2_f32(gb + r11, w11 * wz0, w11 * dz);
        } else if (m4 == 1) {
            red_add_v4_f32(gb + r00 - 1, 0.f, w00 * wz0, w00 * dz, 0.f);
            red_add_v4_f32(gb + r01 - 1, 0.f, w01 * wz0, w01 * dz, 0.f);
            red_add_v4_f32(gb + r10 - 1, 0.f, w10 * wz0, w10 * dz, 0.f);
            red_add_v4_f32(gb + r11 - 1, 0.f, w11 * wz0, w11 * dz, 0.f);
        } else {
            red_add_f32(gb + r00,     w00 * wz0);
            red_add_f32(gb + r00 + 1, w00 * dz);
            red_add_f32(gb + r01,     w01 * wz0);
            red_add_f32(gb + r01 + 1, w01 * dz);
            red_add_f32(gb + r10,     w10 * wz0);
            red_add_f32(gb + r10 + 1, w10 * dz);
            red_add_f32(gb + r11,     w11 * wz0);
            red_add_f32(gb + r11 + 1, w11 * dz);
        }
    } else {
        int ix0 = min(max(ix,     0), GRID_R - 1);
        int ix1 = min(max(ix + 1, 0), GRID_R - 1);
        int iy0 = min(max(iy,     0), GRID_R - 1);
        int iy1 = min(max(iy + 1, 0), GRID_R - 1);
        int iz0 = min(max(iz,     0), GRID_R - 1);
        int iz1 = min(max(iz + 1, 0), GRID_R - 1);
        int rx0 = ix0 * GRID_R * GRID_R, rx1 = ix1 * GRID_R * GRID_R;
        int ry0 = iy0 * GRID_R,          ry1 = iy1 * GRID_R;
        red_add_f32(gb + (rx0 + ry0 + iz0), w00 * wz0);
        red_add_f32(gb + (rx0 + ry0 + iz1), w00 * dz);
        red_add_f32(gb + (rx0 + ry1 + iz0), w01 * wz0);
        red_add_f32(gb + (rx0 + ry1 + iz1), w01 * dz);
        red_add_f32(gb + (rx1 + ry0 + iz0), w10 * wz0);
        red_add_f32(gb + (rx1 + ry0 + iz1), w10 * dz);
        red_add_f32(gb + (rx1 + ry1 + iz0), w11 * wz0);
        red_add_f32(gb + (rx1 + ry1 + iz1), w11 * dz);
    }
}

__device__ __forceinline__ void zero_range(float* __restrict__ base,
                                           long long nfloats)
{
    float4* z = (float4*)base;
    long long n4 = nfloats >> 2;
    long long nthreads = (long long)gridDim.x * blockDim.x;
    float4 zero = make_float4(0.f, 0.f, 0.f, 0.f);
    for (long long i = (long long)blockIdx.x * blockDim.x + threadIdx.x;
         i < n4; i += nthreads)
        z[i] = zero;
}

// y==0: scatter pts[start, start+count) into grid g (cloud base).
// y==1: zero zbase[0, znum) floats.
__global__ __launch_bounds__(256)
void scatter_and_zero_kernel(const float* __restrict__ pts,
                             float* __restrict__ g,
                             int n_per_sample,
                             int start, int count,
                             float* __restrict__ zbase,
                             long long znum)
{
    if (blockIdx.y == 0) {
        scatter_range(pts, g, n_per_sample, start, count);
    } else {
        zero_range(zbase, znum);
    }
}

__global__ __launch_bounds__(256)
void scatter_only_kernel(const float* __restrict__ pts,
                         float* __restrict__ g,
                         int n_per_sample,
                         int start, int count)
{
    scatter_range(pts, g, n_per_sample, start, count);
}

extern "C" void kernel_launch(void* const* d_in, const int* in_sizes, int n_in,
                              void* d_out, int out_size)
{
    const float* pred = (const float*)d_in[0];
    const float* gt   = (const float*)d_in[1];
    float* out = (float*)d_out;

    int b = out_size / (2 * GSZ);                      // 8
    int total_points = in_sizes[0] / 3;                // 524288
    int n = total_points / b;                          // 65536
    long long grid_per_cloud = (long long)b * GSZ;     // 16777216 floats

    // number of leading samples zeroed up-front (pair 0)
    int s0 = (b >= 2) ? 2 : b;
    long long z0 = (long long)s0 * GSZ;                // 4M floats = 16MB
    int pts0 = s0 * n;                                 // 131072

    // L0: expose only pred samples [0, s0) zero-fill
    cudaMemsetAsync(out, 0, (size_t)z0 * sizeof(float));

    if (s0 < b) {
        // L1: scatter pred pts of samples [0,s0) || zero pred samples [s0,b)
        int nblk1 = (pts0 + 255) / 256;                // 512
        scatter_and_zero_kernel<<<dim3(nblk1, 2), 256>>>(
            pred, out, n, 0, pts0,
            out + z0, grid_per_cloud - z0);

        // L2: scatter remaining pred pts || zero gt half
        int ptsR = total_points - pts0;                // 393216
        int nblk2 = (ptsR + 255) / 256;                // 1536
        scatter_and_zero_kernel<<<dim3(nblk2, 2), 256>>>(
            pred, out, n, pts0, ptsR,
            out + grid_per_cloud, grid_per_cloud);
    } else {
        // degenerate small-b fallback: zero gt under full pred scatter
        int nblk2 = (total_points + 255) / 256;
        scatter_and_zero_kernel<<<dim3(nblk2, 2), 256>>>(
            pred, out, n, 0, total_points,
            out + grid_per_cloud, grid_per_cloud);
    }

    // L3: scatter gt (its grid zeroed in L2's zero role, L2-resident)
    int nblk3 = (total_points + 255) / 256;            // 2048
    scatter_only_kernel<<<nblk3, 256>>>(gt, out + grid_per_cloud, n,
                                        0, total_points);
}